// round 3
// baseline (speedup 1.0000x reference)
#include <cuda_runtime.h>

// Shapes fixed by the problem: L=1024, D=640, K=32, M=64
#define LMAX 1024
#define MM   64
#define KE   34    // e_scalar length (etype, pij, 32 rbf)

typedef unsigned long long u64;

// scratch: node projection + bias, 1024 x 64 fp32 = 256 KB (L2-resident)
__device__ float g_nb[LMAX * MM];

// ---- packed fp32x2 helpers (sm_103a dual-fp32 path) -----------------------
__device__ __forceinline__ u64 pack2(float lo, float hi) {
    u64 r; asm("mov.b64 %0, {%1, %2};" : "=l"(r) : "f"(lo), "f"(hi)); return r;
}
__device__ __forceinline__ u64 ffma2(u64 a, u64 b, u64 c) {
    u64 d; asm("fma.rn.f32x2 %0, %1, %2, %3;" : "=l"(d) : "l"(a), "l"(b), "l"(c));
    return d;
}
__device__ __forceinline__ float2 unpack2(u64 v) {
    unsigned lo, hi; asm("mov.b64 {%0, %1}, %2;" : "=r"(lo), "=r"(hi) : "l"(v));
    float2 f; f.x = __uint_as_float(lo); f.y = __uint_as_float(hi); return f;
}

// ---------------------------------------------------------------------------
// Kernel 1: nb[j,m] = sum_d S[j,d] * W_node[d,m] + b_edge[m]
// 128 blocks x 8 rows, 256 threads, register double-buffered staging
// ---------------------------------------------------------------------------
__global__ void __launch_bounds__(256) node_proj_kernel(
    const float* __restrict__ S,
    const float* __restrict__ W_node,
    const float* __restrict__ b_edge,
    int L, int D)
{
    const int m  = threadIdx.x & 63;
    const int jr = threadIdx.x >> 6;     // 0..3
    const int j0 = blockIdx.x * 8;

    __shared__ float sS[8][64];
    __shared__ float sW[64][65];

    float a0 = 0.f, a1 = 0.f;
    float wreg[16], s0, s1;

    // prefetch tile 0
    s0 = S[(size_t)(j0 + jr) * D + m];
    s1 = S[(size_t)(j0 + jr + 4) * D + m];
    #pragma unroll
    for (int r = 0; r < 16; r++)
        wreg[r] = W_node[(size_t)(r * 4 + jr) * MM + m];

    for (int d0 = 0; d0 < D; d0 += 64) {
        sS[jr][m]     = s0;
        sS[jr + 4][m] = s1;
        #pragma unroll
        for (int r = 0; r < 16; r++)
            sW[r * 4 + jr][m] = wreg[r];
        __syncthreads();
        int dn = d0 + 64;
        if (dn < D) {
            s0 = S[(size_t)(j0 + jr) * D + dn + m];
            s1 = S[(size_t)(j0 + jr + 4) * D + dn + m];
            #pragma unroll
            for (int r = 0; r < 16; r++)
                wreg[r] = W_node[(size_t)(dn + r * 4 + jr) * MM + m];
        }
        #pragma unroll
        for (int d = 0; d < 64; d++) {
            float w = sW[d][m];
            a0 = fmaf(sS[jr][d], w, a0);
            a1 = fmaf(sS[jr + 4][d], w, a1);
        }
        __syncthreads();
    }
    float b = b_edge[m];
    g_nb[(j0 + jr) * MM + m]     = a0 + b;
    g_nb[(j0 + jr + 4) * MM + m] = a1 + b;
}

// ---------------------------------------------------------------------------
// Kernel 2: one row per block (grid L, 128 threads). Lane-pair per edge:
// parity p owns interleaved m-set {8g+4p .. 8g+4p+3}, acc = 16 packed f32x2.
// No intra-chunk barriers, no smem round trip for u.
// ---------------------------------------------------------------------------
__global__ void __launch_bounds__(128, 5) edge_kernel(
    const float* __restrict__ P,
    const float* __restrict__ xyz,
    const float* __restrict__ rbf_mu,
    const float* __restrict__ rbf_sigma,
    const float* __restrict__ W_edge,
    const float* __restrict__ w_out,
    float* __restrict__ out,
    int L)
{
    __shared__ __align__(16) float sW[KE * MM];    // 8704 B, [k][m]
    __shared__ __align__(16) float sWo[MM];
    __shared__ float sMu[32], sI2[32];
    __shared__ int   sList[LMAX];
    __shared__ float sPij[LMAX];
    __shared__ float sDx[LMAX], sDy[LMAX], sDz[LMAX], sD[LMAX];
    __shared__ int   wsum[4];
    __shared__ float sred[4][3];

    const int tid  = threadIdx.x;
    const int lane = tid & 31;
    const int wrp  = tid >> 5;
    const int i    = blockIdx.x;

    for (int t = tid; t < KE * MM; t += 128) sW[t] = W_edge[t];
    if (tid < MM) sWo[tid] = w_out[tid];
    if (tid < 32) {
        sMu[tid] = rbf_mu[tid];
        float s = rbf_sigma[tid];
        sI2[tid] = 1.f / (2.f * s * s);
    }
    const float xi = xyz[i * 3 + 0];
    const float yi = xyz[i * 3 + 1];
    const float zi = xyz[i * 3 + 2];

    // ---- deterministic compaction: thread owns 8 consecutive j ----
    const float4* Prow = reinterpret_cast<const float4*>(P + (size_t)i * L);
    float4 pa = Prow[tid * 2], pb = Prow[tid * 2 + 1];
    float pv[8] = {pa.x, pa.y, pa.z, pa.w, pb.x, pb.y, pb.z, pb.w};
    int myj[8]; float myp[8]; int c = 0;
    const int jb = tid * 8;
    #pragma unroll
    for (int r = 0; r < 8; r++) {
        int j = jb + r;
        bool bb = (j == i + 1);
        bool ct = (pv[r] > 0.2f) && (j > i + 2);
        if (bb || ct) { myj[c] = j; myp[c] = bb ? 1.f : pv[r]; c++; }
    }
    int inc = c;
    #pragma unroll
    for (int off = 1; off < 32; off <<= 1) {
        int v = __shfl_up_sync(0xffffffffu, inc, off);
        if (lane >= off) inc += v;
    }
    if (lane == 31) wsum[wrp] = inc;
    __syncthreads();
    int offset = inc - c;
    int total  = 0;
    #pragma unroll
    for (int q = 0; q < 4; q++) {
        int wv = wsum[q];
        if (q < wrp) offset += wv;
        total += wv;
    }
    for (int t = 0; t < c; t++) { sList[offset + t] = myj[t]; sPij[offset + t] = myp[t]; }
    __syncthreads();

    const int ntch   = (total + 15) >> 4;   // 16-edge chunks
    const int padded = ntch << 4;

    // ---- per-edge geometry into smem (padded slots zeroed, j=0) ----
    for (int e = tid; e < padded; e += 128) {
        if (e < total) {
            int j = sList[e];
            float dx = xyz[3 * j + 0] - xi;
            float dy = xyz[3 * j + 1] - yi;
            float dz = xyz[3 * j + 2] - zi;
            sDx[e] = dx; sDy[e] = dy; sDz[e] = dz;
            sD[e]  = sqrtf(fmaf(dx, dx, fmaf(dy, dy, fmaf(dz, dz, 1e-12f))));
        } else {
            sList[e] = 0; sPij[e] = 0.f;
            sDx[e] = 0.f; sDy[e] = 0.f; sDz[e] = 0.f; sD[e] = 0.f;
        }
    }
    __syncthreads();

    // ---- main loop: warp-independent 16-edge chunks ----
    float ax = 0.f, ay = 0.f, az = 0.f;
    const int p = lane & 1;                 // m-half parity

    for (int cI = wrp; cI < ntch; cI += 4) {
        const int le = (cI << 4) + (lane >> 1);
        const int j    = sList[le];
        const float pij = sPij[le];
        const float dxv = sDx[le], dyv = sDy[le], dzv = sDz[le];
        const float dd  = sD[le];
        const float et  = (j == i + 1) ? 0.f : 1.f;

        // acc init from node projection (interleaved-m gather: 1 line/inst-pair)
        u64 acc[16];
        const float* nb = g_nb + j * MM + p * 4;
        #pragma unroll
        for (int q = 0; q < 8; q++) {
            ulonglong2 v = *reinterpret_cast<const ulonglong2*>(nb + q * 8);
            acc[2 * q] = v.x; acc[2 * q + 1] = v.y;
        }

        // k = 0 (etype), k = 1 (pij)
        {
            u64 uk = pack2(et, et);
            const float* wb = sW + p * 4;
            #pragma unroll
            for (int q = 0; q < 8; q++) {
                ulonglong2 wv = *reinterpret_cast<const ulonglong2*>(wb + q * 8);
                acc[2 * q]     = ffma2(uk, wv.x, acc[2 * q]);
                acc[2 * q + 1] = ffma2(uk, wv.y, acc[2 * q + 1]);
            }
        }
        {
            u64 uk = pack2(pij, pij);
            const float* wb = sW + MM + p * 4;
            #pragma unroll
            for (int q = 0; q < 8; q++) {
                ulonglong2 wv = *reinterpret_cast<const ulonglong2*>(wb + q * 8);
                acc[2 * q]     = ffma2(uk, wv.x, acc[2 * q]);
                acc[2 * q + 1] = ffma2(uk, wv.y, acc[2 * q + 1]);
            }
        }
        // k = 2..33 : RBF features
        #pragma unroll
        for (int k = 0; k < 32; k++) {
            float t = dd - sMu[k];
            float u = __expf(-t * t * sI2[k]);
            u64 uk = pack2(u, u);
            const float* wb = sW + (k + 2) * MM + p * 4;
            #pragma unroll
            for (int q = 0; q < 8; q++) {
                ulonglong2 wv = *reinterpret_cast<const ulonglong2*>(wb + q * 8);
                acc[2 * q]     = ffma2(uk, wv.x, acc[2 * q]);
                acc[2 * q + 1] = ffma2(uk, wv.y, acc[2 * q + 1]);
            }
        }

        // epilogue: relu . w_out over this lane's 32 m, combine pair, gate
        float gg = 0.f;
        #pragma unroll
        for (int q = 0; q < 8; q++) {
            float4 wo = *reinterpret_cast<const float4*>(sWo + q * 8 + p * 4);
            float2 a = unpack2(acc[2 * q]);
            float2 b = unpack2(acc[2 * q + 1]);
            gg = fmaf(fmaxf(a.x, 0.f), wo.x,
                 fmaf(fmaxf(a.y, 0.f), wo.y,
                 fmaf(fmaxf(b.x, 0.f), wo.z,
                 fmaf(fmaxf(b.y, 0.f), wo.w, gg))));
        }
        gg += __shfl_xor_sync(0xffffffffu, gg, 1);
        if (p == 0 && le < total) {
            float gate = 1.f / (1.f + __expf(-gg));
            ax = fmaf(gate, dxv, ax);
            ay = fmaf(gate, dyv, ay);
            az = fmaf(gate, dzv, az);
        }
    }

    // ---- deterministic block reduction ----
    #pragma unroll
    for (int off = 16; off; off >>= 1) {
        ax += __shfl_down_sync(0xffffffffu, ax, off);
        ay += __shfl_down_sync(0xffffffffu, ay, off);
        az += __shfl_down_sync(0xffffffffu, az, off);
    }
    if (lane == 0) { sred[wrp][0] = ax; sred[wrp][1] = ay; sred[wrp][2] = az; }
    __syncthreads();
    if (tid == 0) {
        float tx = 0.f, ty = 0.f, tz = 0.f;
        #pragma unroll
        for (int q = 0; q < 4; q++) { tx += sred[q][0]; ty += sred[q][1]; tz += sred[q][2]; }
        out[i * 3 + 0] = xi + tx;
        out[i * 3 + 1] = yi + ty;
        out[i * 3 + 2] = zi + tz;
    }
}

// ---------------------------------------------------------------------------
extern "C" void kernel_launch(void* const* d_in, const int* in_sizes, int n_in,
                              void* d_out, int out_size)
{
    const float* S         = (const float*)d_in[0];
    const float* P         = (const float*)d_in[1];
    const float* xyz       = (const float*)d_in[2];
    const float* rbf_mu    = (const float*)d_in[3];
    const float* rbf_sigma = (const float*)d_in[4];
    const float* W_edge    = (const float*)d_in[5];
    const float* b_edge    = (const float*)d_in[6];
    const float* W_node    = (const float*)d_in[7];
    const float* w_out     = (const float*)d_in[8];
    float* out = (float*)d_out;

    int L = in_sizes[2] / 3;          // 1024
    int D = in_sizes[0] / L;          // 640

    node_proj_kernel<<<L / 8, 256>>>(S, W_node, b_edge, L, D);
    edge_kernel<<<L, 128>>>(P, xyz, rbf_mu, rbf_sigma, W_edge, w_out, out, L);
}